// round 3
// baseline (speedup 1.0000x reference)
#include <cuda_runtime.h>
#include <cstdint>

#define VOCAB 50000
#define EDIM  256
#define HDIM  256
#define BATCH 64
#define TLEN  2048

typedef unsigned long long u64;

// proj_table[v][h] = sum_e emb[v][e] * W_ih[h][e]   (51.2 MB device scratch)
__device__ float g_proj[VOCAB * HDIM];

// ---------------------------------------------------------------------------
// Kernel A: proj = emb @ W_ih^T   (NT SGEMM, C[50000,256])  -- unchanged (R1)
// ---------------------------------------------------------------------------
__global__ __launch_bounds__(256) void proj_kernel(const float* __restrict__ emb,
                                                   const float* __restrict__ Wih) {
    __shared__ float As[32][128];
    __shared__ float Bs[32][128];

    const int n0 = blockIdx.x * 128;
    const int m0 = blockIdx.y * 128;
    const int tid = threadIdx.x;
    const int tx = tid & 15;
    const int ty = tid >> 4;

    float acc[8][8];
#pragma unroll
    for (int a = 0; a < 8; a++)
#pragma unroll
        for (int bb = 0; bb < 8; bb++) acc[a][bb] = 0.0f;

    for (int kc = 0; kc < EDIM; kc += 32) {
#pragma unroll
        for (int q = 0; q < 4; q++) {
            int fid = tid + 256 * q;
            int row = fid >> 3;
            int col = fid & 7;
            float4 av = make_float4(0.f, 0.f, 0.f, 0.f);
            int m = m0 + row;
            if (m < VOCAB)
                av = __ldg((const float4*)(emb + (size_t)m * EDIM + kc + col * 4));
            As[col * 4 + 0][row] = av.x;
            As[col * 4 + 1][row] = av.y;
            As[col * 4 + 2][row] = av.z;
            As[col * 4 + 3][row] = av.w;
            float4 bv = __ldg((const float4*)(Wih + (size_t)(n0 + row) * EDIM + kc + col * 4));
            Bs[col * 4 + 0][row] = bv.x;
            Bs[col * 4 + 1][row] = bv.y;
            Bs[col * 4 + 2][row] = bv.z;
            Bs[col * 4 + 3][row] = bv.w;
        }
        __syncthreads();

#pragma unroll
        for (int k = 0; k < 32; k++) {
            float a[8], b[8];
            *(float4*)&a[0] = *(const float4*)&As[k][ty * 8];
            *(float4*)&a[4] = *(const float4*)&As[k][ty * 8 + 4];
            *(float4*)&b[0] = *(const float4*)&Bs[k][tx * 8];
            *(float4*)&b[4] = *(const float4*)&Bs[k][tx * 8 + 4];
#pragma unroll
            for (int ii = 0; ii < 8; ii++)
#pragma unroll
                for (int jj = 0; jj < 8; jj++) acc[ii][jj] += a[ii] * b[jj];
        }
        __syncthreads();
    }

#pragma unroll
    for (int ii = 0; ii < 8; ii++) {
        int m = m0 + ty * 8 + ii;
        if (m < VOCAB) {
            float4 v0 = make_float4(acc[ii][0], acc[ii][1], acc[ii][2], acc[ii][3]);
            float4 v1 = make_float4(acc[ii][4], acc[ii][5], acc[ii][6], acc[ii][7]);
            *(float4*)(g_proj + (size_t)m * HDIM + n0 + tx * 8)     = v0;
            *(float4*)(g_proj + (size_t)m * HDIM + n0 + tx * 8 + 4) = v1;
        }
    }
}

// ---------------------------------------------------------------------------
// Kernel B: RNN scan. 64 clusters x 2 CTAs. mbarrier ping-pong sync,
// intra-warp shfl reduction, own/peer K-split around the wait.
// Warp w owns outputs w*4..w*4+3 (local half); lane group g = l&7 handles
// K elements {half + q*32 + g*4 .. +3} (bank-conflict-free, broadcast).
// ---------------------------------------------------------------------------
__device__ __forceinline__ void fma2(u64& acc, u64 a, u64 b) {
    asm("fma.rn.f32x2 %0, %1, %2, %0;" : "+l"(acc) : "l"(a), "l"(b));
}
__device__ __forceinline__ uint32_t s2u(const void* p) {
    return (uint32_t)__cvta_generic_to_shared(p);
}
__device__ __forceinline__ uint32_t mapa_u32(uint32_t a, uint32_t r) {
    uint32_t ret;
    asm("mapa.shared::cluster.u32 %0, %1, %2;" : "=r"(ret) : "r"(a), "r"(r));
    return ret;
}
__device__ __forceinline__ void st_remote_f32(uint32_t ra, float v) {
    asm volatile("st.shared::cluster.f32 [%0], %1;" :: "r"(ra), "f"(v) : "memory");
}
__device__ __forceinline__ void mbar_init(uint32_t a, uint32_t cnt) {
    asm volatile("mbarrier.init.shared.b64 [%0], %1;" :: "r"(a), "r"(cnt) : "memory");
}
__device__ __forceinline__ void mbar_arrive_rel_remote(uint32_t ra) {
    asm volatile("mbarrier.arrive.release.cluster.shared::cluster.b64 _, [%0];"
                 :: "r"(ra) : "memory");
}
__device__ __forceinline__ void mbar_wait_acq(uint32_t a, uint32_t par) {
    asm volatile(
        "{\n\t.reg .pred P;\n"
        "LW%=:\n\t"
        "mbarrier.try_wait.parity.acquire.cluster.shared::cta.b64 P, [%0], %1, 0x989680;\n\t"
        "@!P bra LW%=;\n\t}"
        :: "r"(a), "r"(par) : "memory");
}

__global__ void __cluster_dims__(2, 1, 1) __launch_bounds__(1024, 1)
scan_kernel(const int* __restrict__ reviews, const int* __restrict__ lengths,
            const float* __restrict__ Whh, const float* __restrict__ Wcls,
            const float* __restrict__ bcls, float* __restrict__ out) {
    __shared__ __align__(16) float hbuf[2][HDIM];
    __shared__ int toks[TLEN];
    __shared__ __align__(8) u64 mbar[2];

    const int tid  = threadIdx.x;
    const int w    = tid >> 5;
    const int l    = tid & 31;
    const int g    = l & 7;                 // K-slice within output group
    const int i    = w * 4 + (l >> 3);      // local output index 0..127
    const int b    = blockIdx.x >> 1;
    const int rank = blockIdx.x & 1;
    const int peer = rank ^ 1;
    const int len  = lengths[b];
    const int ownK  = rank * 128;           // K range produced locally
    const int peerK = 128 - ownK;

    if (tid == 0) {
        mbar_init(s2u(&mbar[0]), 128);
        mbar_init(s2u(&mbar[1]), 128);
    }
    for (int idx = tid; idx < TLEN; idx += 1024)
        toks[idx] = reviews[b * TLEN + idx];
    if (tid < HDIM) hbuf[0][tid] = 0.0f;
    __syncthreads();
    // peer's mbarrier init must be visible before any remote arrive
    asm volatile("barrier.cluster.arrive.aligned;" ::: "memory");
    asm volatile("barrier.cluster.wait.aligned;" ::: "memory");

    // W_hh[ownK+i][.] split into own-half / peer-half K, packed f32x2
    u64 wOwn[8], wPeer[8];
    {
        const float* wr = Whh + (size_t)(ownK + i) * HDIM;
#pragma unroll
        for (int q = 0; q < 4; q++) {
            ulonglong2 a = *(const ulonglong2*)(wr + ownK + q * 32 + g * 4);
            wOwn[2 * q]     = a.x;
            wOwn[2 * q + 1] = a.y;
            ulonglong2 c = *(const ulonglong2*)(wr + peerK + q * 32 + g * 4);
            wPeer[2 * q]     = c.x;
            wPeer[2 * q + 1] = c.y;
        }
    }

    const bool writer = (g == 0);
    const int  ow     = ownK + i;
    const uint32_t mb0 = s2u(&mbar[0]);
    const uint32_t mb1 = s2u(&mbar[1]);
    const uint32_t rM0 = mapa_u32(mb0, peer);
    const uint32_t rM1 = mapa_u32(mb1, peer);
    const uint32_t rH0 = mapa_u32(s2u(&hbuf[0][ow]), peer);
    const uint32_t rH1 = mapa_u32(s2u(&hbuf[1][ow]), peer);

    float xp_cur = 0.0f;
    if (writer) xp_cur = __ldg(g_proj + (size_t)toks[0] * HDIM + ow);

    uint32_t ph0 = 0, ph1 = 0;

    for (int t = 0; t < len; ++t) {
        const int p = t & 1, pn = p ^ 1;

        // prefetch next step's xp (hidden under FMA + wait)
        float xp_next = 0.0f;
        if (writer) {
            int tn = (t + 1 < len) ? (t + 1) : t;
            xp_next = __ldg(g_proj + (size_t)toks[tn] * HDIM + ow);
        }

        u64 acc = 0ull;
        const float* hb = hbuf[p];
        // own-half K: locally produced, valid after prior __syncthreads
#pragma unroll
        for (int q = 0; q < 4; q++) {
            ulonglong2 hh = *(const ulonglong2*)(hb + ownK + q * 32 + g * 4);
            fma2(acc, wOwn[2 * q],     hh.x);
            fma2(acc, wOwn[2 * q + 1], hh.y);
        }
        // wait for peer's half (t=0 is all-zero locally, no wait)
        if (t > 0) {
            if (p == 0) { mbar_wait_acq(mb0, ph0); ph0 ^= 1; }
            else        { mbar_wait_acq(mb1, ph1); ph1 ^= 1; }
        }
#pragma unroll
        for (int q = 0; q < 4; q++) {
            ulonglong2 hh = *(const ulonglong2*)(hb + peerK + q * 32 + g * 4);
            fma2(acc, wPeer[2 * q],     hh.x);
            fma2(acc, wPeer[2 * q + 1], hh.y);
        }
        float2 af = *(float2*)&acc;
        float s = af.x + af.y;
        s += __shfl_xor_sync(0xffffffffu, s, 1);
        s += __shfl_xor_sync(0xffffffffu, s, 2);
        s += __shfl_xor_sync(0xffffffffu, s, 4);

        if (writer) {
            float v = tanhf(s + xp_cur);
            hbuf[pn][ow] = v;                              // local copy
            st_remote_f32(pn ? rH1 : rH0, v);              // peer copy
            mbar_arrive_rel_remote(pn ? rM1 : rM0);        // release my store
            xp_cur = xp_next;
        }
        __syncthreads();                                   // local h visible CTA-wide
    }

    // classifier: rank 0 assembles full final h
    if (rank == 0 && tid < 64) {
        const int pf = len & 1;
        mbar_wait_acq(pf ? mb1 : mb0, pf ? ph1 : ph0);     // peer's final half
        int c = tid >> 5, lane = tid & 31;
        const float* hf = hbuf[pf];
        float sum = 0.0f;
#pragma unroll
        for (int m = 0; m < 8; m++)
            sum += Wcls[c * HDIM + lane + 32 * m] * hf[lane + 32 * m];
#pragma unroll
        for (int o = 16; o > 0; o >>= 1) sum += __shfl_down_sync(0xffffffffu, sum, o);
        if (lane == 0) out[b * 2 + c] = sum + bcls[c];
    }

    // keep both CTAs alive until all cross-CTA traffic has landed
    asm volatile("barrier.cluster.arrive.aligned;" ::: "memory");
    asm volatile("barrier.cluster.wait.aligned;" ::: "memory");
}

// ---------------------------------------------------------------------------
extern "C" void kernel_launch(void* const* d_in, const int* in_sizes, int n_in,
                              void* d_out, int out_size) {
    const int*   reviews = (const int*)d_in[0];
    const int*   lengths = (const int*)d_in[1];
    const float* emb     = (const float*)d_in[2];
    const float* Wih     = (const float*)d_in[3];
    const float* Whh     = (const float*)d_in[4];
    const float* Wcls    = (const float*)d_in[5];
    const float* bcls    = (const float*)d_in[6];
    float*       out     = (float*)d_out;

    dim3 gA(2, (VOCAB + 127) / 128);
    proj_kernel<<<gA, 256>>>(emb, Wih);

    scan_kernel<<<BATCH * 2, 1024>>>(reviews, lengths, Whh, Wcls, bcls, out);
}

// round 4
// speedup vs baseline: 1.0606x; 1.0606x over previous
#include <cuda_runtime.h>
#include <cstdint>

#define VOCAB 50000
#define EDIM  256
#define HDIM  256
#define BATCH 64
#define TLEN  2048

typedef unsigned long long u64;

// proj_table[v][h] = sum_e emb[v][e] * W_ih[h][e]   (51.2 MB device scratch)
__device__ float g_proj[VOCAB * HDIM];

// ---------------------------------------------------------------------------
// Kernel A: proj = emb @ W_ih^T   (NT SGEMM, C[50000,256])  -- unchanged
// ---------------------------------------------------------------------------
__global__ __launch_bounds__(256) void proj_kernel(const float* __restrict__ emb,
                                                   const float* __restrict__ Wih) {
    __shared__ float As[32][128];
    __shared__ float Bs[32][128];

    const int n0 = blockIdx.x * 128;
    const int m0 = blockIdx.y * 128;
    const int tid = threadIdx.x;
    const int tx = tid & 15;
    const int ty = tid >> 4;

    float acc[8][8];
#pragma unroll
    for (int a = 0; a < 8; a++)
#pragma unroll
        for (int bb = 0; bb < 8; bb++) acc[a][bb] = 0.0f;

    for (int kc = 0; kc < EDIM; kc += 32) {
#pragma unroll
        for (int q = 0; q < 4; q++) {
            int fid = tid + 256 * q;
            int row = fid >> 3;
            int col = fid & 7;
            float4 av = make_float4(0.f, 0.f, 0.f, 0.f);
            int m = m0 + row;
            if (m < VOCAB)
                av = __ldg((const float4*)(emb + (size_t)m * EDIM + kc + col * 4));
            As[col * 4 + 0][row] = av.x;
            As[col * 4 + 1][row] = av.y;
            As[col * 4 + 2][row] = av.z;
            As[col * 4 + 3][row] = av.w;
            float4 bv = __ldg((const float4*)(Wih + (size_t)(n0 + row) * EDIM + kc + col * 4));
            Bs[col * 4 + 0][row] = bv.x;
            Bs[col * 4 + 1][row] = bv.y;
            Bs[col * 4 + 2][row] = bv.z;
            Bs[col * 4 + 3][row] = bv.w;
        }
        __syncthreads();

#pragma unroll
        for (int k = 0; k < 32; k++) {
            float a[8], b[8];
            *(float4*)&a[0] = *(const float4*)&As[k][ty * 8];
            *(float4*)&a[4] = *(const float4*)&As[k][ty * 8 + 4];
            *(float4*)&b[0] = *(const float4*)&Bs[k][tx * 8];
            *(float4*)&b[4] = *(const float4*)&Bs[k][tx * 8 + 4];
#pragma unroll
            for (int ii = 0; ii < 8; ii++)
#pragma unroll
                for (int jj = 0; jj < 8; jj++) acc[ii][jj] += a[ii] * b[jj];
        }
        __syncthreads();
    }

#pragma unroll
    for (int ii = 0; ii < 8; ii++) {
        int m = m0 + ty * 8 + ii;
        if (m < VOCAB) {
            float4 v0 = make_float4(acc[ii][0], acc[ii][1], acc[ii][2], acc[ii][3]);
            float4 v1 = make_float4(acc[ii][4], acc[ii][5], acc[ii][6], acc[ii][7]);
            *(float4*)(g_proj + (size_t)m * HDIM + n0 + tx * 8)     = v0;
            *(float4*)(g_proj + (size_t)m * HDIM + n0 + tx * 8 + 4) = v1;
        }
    }
}

// ---------------------------------------------------------------------------
// Kernel B: RNN scan. 64 clusters x 2 CTAs.
// Sync per step: 32 x st.async.v4 (16B, data + complete_tx) into peer smem,
// peer posts ONE arrive.expect_tx(512) on its local barrier. No per-thread
// remote arrives (the R2 mistake).
// ---------------------------------------------------------------------------
__device__ __forceinline__ void fma2(u64& acc, u64 a, u64 b) {
    asm("fma.rn.f32x2 %0, %1, %2, %0;" : "+l"(acc) : "l"(a), "l"(b));
}
__device__ __forceinline__ uint32_t s2u(const void* p) {
    return (uint32_t)__cvta_generic_to_shared(p);
}
__device__ __forceinline__ uint32_t mapa_u32(uint32_t a, uint32_t r) {
    uint32_t ret;
    asm("mapa.shared::cluster.u32 %0, %1, %2;" : "=r"(ret) : "r"(a), "r"(r));
    return ret;
}
__device__ __forceinline__ void mbar_init(uint32_t a, uint32_t cnt) {
    asm volatile("mbarrier.init.shared.b64 [%0], %1;" :: "r"(a), "r"(cnt) : "memory");
}
__device__ __forceinline__ void mbar_expect_tx(uint32_t a, uint32_t bytes) {
    asm volatile("mbarrier.arrive.expect_tx.shared.b64 _, [%0], %1;"
                 :: "r"(a), "r"(bytes) : "memory");
}
__device__ __forceinline__ void st_async_v4(uint32_t raddr, float x, float y,
                                            float z, float w, uint32_t rmbar) {
    asm volatile(
        "st.async.shared::cluster.mbarrier::complete_tx::bytes.v4.f32 "
        "[%0], {%1, %2, %3, %4}, [%5];"
        :: "r"(raddr), "f"(x), "f"(y), "f"(z), "f"(w), "r"(rmbar) : "memory");
}
__device__ __forceinline__ void mbar_wait_acq(uint32_t a, uint32_t par) {
    asm volatile(
        "{\n\t.reg .pred P;\n"
        "LW%=:\n\t"
        "mbarrier.try_wait.parity.acquire.cluster.shared::cta.b64 P, [%0], %1, 0x989680;\n\t"
        "@!P bra LW%=;\n\t}"
        :: "r"(a), "r"(par) : "memory");
}

__global__ void __cluster_dims__(2, 1, 1) __launch_bounds__(1024, 1)
scan_kernel(const int* __restrict__ reviews, const int* __restrict__ lengths,
            const float* __restrict__ Whh, const float* __restrict__ Wcls,
            const float* __restrict__ bcls, float* __restrict__ out) {
    __shared__ __align__(16) float hbuf[2][HDIM];
    __shared__ int toks[TLEN];
    __shared__ __align__(8) u64 mbar[2];

    const int tid  = threadIdx.x;
    const int w    = tid >> 5;
    const int l    = tid & 31;
    const int g    = l & 7;                 // K-slice within output group
    const int i    = w * 4 + (l >> 3);      // local output index 0..127
    const int b    = blockIdx.x >> 1;
    const int rank = blockIdx.x & 1;
    const int peer = rank ^ 1;
    const int len  = lengths[b];
    const int ownK  = rank * 128;           // h range produced locally
    const int peerK = 128 - ownK;

    if (tid == 0) {
        mbar_init(s2u(&mbar[0]), 1);        // 1 arrive (expect_tx poster) + 512B tx
        mbar_init(s2u(&mbar[1]), 1);
    }
    for (int idx = tid; idx < TLEN; idx += 1024)
        toks[idx] = reviews[b * TLEN + idx];
    if (tid < HDIM) hbuf[0][tid] = 0.0f;
    __syncthreads();
    // peer's mbarrier init must be visible before any st.async targets it
    asm volatile("barrier.cluster.arrive.aligned;" ::: "memory");
    asm volatile("barrier.cluster.wait.aligned;" ::: "memory");

    // W_hh[ownK+i][.] split own-half / peer-half K, packed f32x2
    u64 wOwn[8], wPeer[8];
    {
        const float* wr = Whh + (size_t)(ownK + i) * HDIM;
#pragma unroll
        for (int q = 0; q < 4; q++) {
            ulonglong2 a = *(const ulonglong2*)(wr + ownK + q * 32 + g * 4);
            wOwn[2 * q]     = a.x;
            wOwn[2 * q + 1] = a.y;
            ulonglong2 c = *(const ulonglong2*)(wr + peerK + q * 32 + g * 4);
            wPeer[2 * q]     = c.x;
            wPeer[2 * q + 1] = c.y;
        }
    }

    const bool writer = (g == 0);
    const int  ow     = ownK + i;
    const uint32_t mb0 = s2u(&mbar[0]);
    const uint32_t mb1 = s2u(&mbar[1]);
    // this warp's float4 slot in the peer's hbuf, both phases + peer barriers
    const uint32_t rD0 = mapa_u32(s2u(&hbuf[0][ownK + w * 4]), peer);
    const uint32_t rD1 = mapa_u32(s2u(&hbuf[1][ownK + w * 4]), peer);
    const uint32_t rB0 = mapa_u32(mb0, peer);
    const uint32_t rB1 = mapa_u32(mb1, peer);

    float xp_cur = 0.0f;
    if (writer) xp_cur = __ldg(g_proj + (size_t)toks[0] * HDIM + ow);

    uint32_t ph0 = 0, ph1 = 0;

    for (int t = 0; t < len; ++t) {
        const int p = t & 1, pn = p ^ 1;

        // post the single expected-arrive for the phase receiving peer's step-t data
        if (tid == 0) mbar_expect_tx(pn ? mb1 : mb0, 512);

        // prefetch next step's xp (hidden under FMA + wait)
        float xp_next = 0.0f;
        if (writer) {
            int tn = (t + 1 < len) ? (t + 1) : t;
            xp_next = __ldg(g_proj + (size_t)toks[tn] * HDIM + ow);
        }

        u64 acc = 0ull;
        const float* hb = hbuf[p];
        // own-half K: locally produced, valid after prior __syncthreads
#pragma unroll
        for (int q = 0; q < 4; q++) {
            ulonglong2 hh = *(const ulonglong2*)(hb + ownK + q * 32 + g * 4);
            fma2(acc, wOwn[2 * q],     hh.x);
            fma2(acc, wOwn[2 * q + 1], hh.y);
        }
        // wait for peer's half (t=0 reads the zero-init buffer, no wait)
        if (t > 0) {
            if (p == 0) { mbar_wait_acq(mb0, ph0); ph0 ^= 1; }
            else        { mbar_wait_acq(mb1, ph1); ph1 ^= 1; }
        }
#pragma unroll
        for (int q = 0; q < 4; q++) {
            ulonglong2 hh = *(const ulonglong2*)(hb + peerK + q * 32 + g * 4);
            fma2(acc, wPeer[2 * q],     hh.x);
            fma2(acc, wPeer[2 * q + 1], hh.y);
        }
        float2 af = *(float2*)&acc;
        float s = af.x + af.y;
        s += __shfl_xor_sync(0xffffffffu, s, 1);
        s += __shfl_xor_sync(0xffffffffu, s, 2);
        s += __shfl_xor_sync(0xffffffffu, s, 4);

        float v = 0.0f;
        if (writer) {                       // lanes 0,8,16,24: outputs w*4+0..3
            v = tanhf(s + xp_cur);
            xp_cur = xp_next;
        }
        // gather the 4 outputs to lane 0
        float v1 = __shfl_sync(0xffffffffu, v, 8);
        float v2 = __shfl_sync(0xffffffffu, v, 16);
        float v3 = __shfl_sync(0xffffffffu, v, 24);
        if (l == 0) {
            *(float4*)&hbuf[pn][ownK + w * 4] = make_float4(v, v1, v2, v3);
            st_async_v4(pn ? rD1 : rD0, v, v1, v2, v3, pn ? rB1 : rB0);
        }
        __syncthreads();                    // local half visible CTA-wide
    }

    // classifier: rank 0 assembles full final h
    if (rank == 0 && tid < 64) {
        const int pf = len & 1;
        mbar_wait_acq(pf ? mb1 : mb0, pf ? ph1 : ph0);   // peer's final half
        int c = tid >> 5, lane = tid & 31;
        const float* hf = hbuf[pf];
        float sum = 0.0f;
#pragma unroll
        for (int m = 0; m < 8; m++)
            sum += Wcls[c * HDIM + lane + 32 * m] * hf[lane + 32 * m];
#pragma unroll
        for (int o = 16; o > 0; o >>= 1) sum += __shfl_down_sync(0xffffffffu, sum, o);
        if (lane == 0) out[b * 2 + c] = sum + bcls[c];
    }

    // keep both CTAs alive until all cross-CTA traffic has landed
    asm volatile("barrier.cluster.arrive.aligned;" ::: "memory");
    asm volatile("barrier.cluster.wait.aligned;" ::: "memory");
}

// ---------------------------------------------------------------------------
extern "C" void kernel_launch(void* const* d_in, const int* in_sizes, int n_in,
                              void* d_out, int out_size) {
    const int*   reviews = (const int*)d_in[0];
    const int*   lengths = (const int*)d_in[1];
    const float* emb     = (const float*)d_in[2];
    const float* Wih     = (const float*)d_in[3];
    const float* Whh     = (const float*)d_in[4];
    const float* Wcls    = (const float*)d_in[5];
    const float* bcls    = (const float*)d_in[6];
    float*       out     = (float*)d_out;

    dim3 gA(2, (VOCAB + 127) / 128);
    proj_kernel<<<gA, 256>>>(emb, Wih);

    scan_kernel<<<BATCH * 2, 1024>>>(reviews, lengths, Whh, Wcls, bcls, out);
}

// round 5
// speedup vs baseline: 1.1839x; 1.1162x over previous
#include <cuda_runtime.h>
#include <cstdint>

#define VOCAB 50000
#define EDIM  256
#define HDIM  256
#define BATCH 64
#define TLEN  2048

typedef unsigned long long u64;

// proj_table[v][h] = sum_e emb[v][e] * W_ih[h][e]   (51.2 MB device scratch)
__device__ float g_proj[VOCAB * HDIM];

// ---------------------------------------------------------------------------
// Kernel A: proj = emb @ W_ih^T   (NT SGEMM, C[50000,256])  -- unchanged
// ---------------------------------------------------------------------------
__global__ __launch_bounds__(256) void proj_kernel(const float* __restrict__ emb,
                                                   const float* __restrict__ Wih) {
    __shared__ float As[32][128];
    __shared__ float Bs[32][128];

    const int n0 = blockIdx.x * 128;
    const int m0 = blockIdx.y * 128;
    const int tid = threadIdx.x;
    const int tx = tid & 15;
    const int ty = tid >> 4;

    float acc[8][8];
#pragma unroll
    for (int a = 0; a < 8; a++)
#pragma unroll
        for (int bb = 0; bb < 8; bb++) acc[a][bb] = 0.0f;

    for (int kc = 0; kc < EDIM; kc += 32) {
#pragma unroll
        for (int q = 0; q < 4; q++) {
            int fid = tid + 256 * q;
            int row = fid >> 3;
            int col = fid & 7;
            float4 av = make_float4(0.f, 0.f, 0.f, 0.f);
            int m = m0 + row;
            if (m < VOCAB)
                av = __ldg((const float4*)(emb + (size_t)m * EDIM + kc + col * 4));
            As[col * 4 + 0][row] = av.x;
            As[col * 4 + 1][row] = av.y;
            As[col * 4 + 2][row] = av.z;
            As[col * 4 + 3][row] = av.w;
            float4 bv = __ldg((const float4*)(Wih + (size_t)(n0 + row) * EDIM + kc + col * 4));
            Bs[col * 4 + 0][row] = bv.x;
            Bs[col * 4 + 1][row] = bv.y;
            Bs[col * 4 + 2][row] = bv.z;
            Bs[col * 4 + 3][row] = bv.w;
        }
        __syncthreads();

#pragma unroll
        for (int k = 0; k < 32; k++) {
            float a[8], b[8];
            *(float4*)&a[0] = *(const float4*)&As[k][ty * 8];
            *(float4*)&a[4] = *(const float4*)&As[k][ty * 8 + 4];
            *(float4*)&b[0] = *(const float4*)&Bs[k][tx * 8];
            *(float4*)&b[4] = *(const float4*)&Bs[k][tx * 8 + 4];
#pragma unroll
            for (int ii = 0; ii < 8; ii++)
#pragma unroll
                for (int jj = 0; jj < 8; jj++) acc[ii][jj] += a[ii] * b[jj];
        }
        __syncthreads();
    }

#pragma unroll
    for (int ii = 0; ii < 8; ii++) {
        int m = m0 + ty * 8 + ii;
        if (m < VOCAB) {
            float4 v0 = make_float4(acc[ii][0], acc[ii][1], acc[ii][2], acc[ii][3]);
            float4 v1 = make_float4(acc[ii][4], acc[ii][5], acc[ii][6], acc[ii][7]);
            *(float4*)(g_proj + (size_t)m * HDIM + n0 + tx * 8)     = v0;
            *(float4*)(g_proj + (size_t)m * HDIM + n0 + tx * 8 + 4) = v1;
        }
    }
}

// ---------------------------------------------------------------------------
// Kernel B: RNN scan. 64 clusters x 2 CTAs of 512 threads.
// Sync: plain st.shared::cluster + barrier.cluster (R1 mechanism, fastest
// measured). Warp owns 8 outputs; lane slice s=l&3 covers float4-blocks
// {4m+s} (interleaved -> contiguous 64B warp h-loads). Reduce = 2 shfl_xor.
// One __syncthreads per step.
// ---------------------------------------------------------------------------
__device__ __forceinline__ void fma2(u64& acc, u64 a, u64 b) {
    asm("fma.rn.f32x2 %0, %1, %2, %0;" : "+l"(acc) : "l"(a), "l"(b));
}
__device__ __forceinline__ u64 add2(u64 a, u64 b) {
    u64 r;
    asm("add.rn.f32x2 %0, %1, %2;" : "=l"(r) : "l"(a), "l"(b));
    return r;
}
__device__ __forceinline__ uint32_t s2u(const void* p) {
    return (uint32_t)__cvta_generic_to_shared(p);
}
__device__ __forceinline__ uint32_t mapa_u32(uint32_t a, uint32_t r) {
    uint32_t ret;
    asm("mapa.shared::cluster.u32 %0, %1, %2;" : "=r"(ret) : "r"(a), "r"(r));
    return ret;
}
__device__ __forceinline__ void st_remote_f32(uint32_t ra, float v) {
    asm volatile("st.shared::cluster.f32 [%0], %1;" :: "r"(ra), "f"(v) : "memory");
}

__global__ void __cluster_dims__(2, 1, 1) __launch_bounds__(512, 1)
scan_kernel(const int* __restrict__ reviews, const int* __restrict__ lengths,
            const float* __restrict__ Whh, const float* __restrict__ Wcls,
            const float* __restrict__ bcls, float* __restrict__ out) {
    __shared__ __align__(16) float hbuf[2][HDIM];
    __shared__ int toks[TLEN];

    const int tid  = threadIdx.x;
    const int w    = tid >> 5;              // 16 warps
    const int l    = tid & 31;
    const int s    = l & 3;                 // K-slice id (interleaved float4 blocks)
    const int i    = w * 8 + (l >> 2);      // local output index 0..127
    const int b    = blockIdx.x >> 1;
    const int rank = blockIdx.x & 1;
    const int peer = rank ^ 1;
    const int len  = lengths[b];
    const int ownK  = rank * 128;           // h range produced locally (floats)
    const int peerK = 128 - ownK;

    for (int idx = tid; idx < TLEN; idx += 512)
        toks[idx] = reviews[b * TLEN + idx];
    if (tid < HDIM) hbuf[0][tid] = 0.0f;

    // W_hh[ownK+i][.]: own-half K-blocks {4m+s}, peer-half K-blocks {4m+s}
    // each block = 4 consecutive floats = 2 packed f32x2.
    u64 wOwn[16], wPeer[16];
    {
        const float* wr = Whh + (size_t)(ownK + i) * HDIM;
#pragma unroll
        for (int m = 0; m < 8; m++) {
            ulonglong2 a = *(const ulonglong2*)(wr + ownK + (4 * m + s) * 4);
            wOwn[2 * m]     = a.x;
            wOwn[2 * m + 1] = a.y;
            ulonglong2 c = *(const ulonglong2*)(wr + peerK + (4 * m + s) * 4);
            wPeer[2 * m]     = c.x;
            wPeer[2 * m + 1] = c.y;
        }
    }
    __syncthreads();

    const bool writer = (s == 0);
    const int  ow     = ownK + i;
    const uint32_t rH0 = mapa_u32(s2u(&hbuf[0][ow]), peer);
    const uint32_t rH1 = mapa_u32(s2u(&hbuf[1][ow]), peer);

    float xp_cur = __ldg(g_proj + (size_t)toks[0] * HDIM + ow);

    // prologue arrive (pairs with t=0 wait; h0 is all-zero locally)
    asm volatile("barrier.cluster.arrive.aligned;" ::: "memory");

    for (int t = 0; t < len; ++t) {
        const int p = t & 1, pn = p ^ 1;

        // prefetch next step's xp (hidden under FMA + barrier wait)
        int tn = (t + 1 < len) ? (t + 1) : t;
        float xp_next = __ldg(g_proj + (size_t)toks[tn] * HDIM + ow);

        const float* hb = hbuf[p];
        u64 a0 = 0ull, a1 = 0ull, a2 = 0ull, a3 = 0ull;
        // own-half K: locally produced, valid after prior __syncthreads
#pragma unroll
        for (int m = 0; m < 8; m += 2) {
            ulonglong2 h0 = *(const ulonglong2*)(hb + ownK + (4 * m + s) * 4);
            ulonglong2 h1 = *(const ulonglong2*)(hb + ownK + (4 * (m + 1) + s) * 4);
            fma2(a0, wOwn[2 * m],     h0.x);
            fma2(a1, wOwn[2 * m + 1], h0.y);
            fma2(a2, wOwn[2 * m + 2], h1.x);
            fma2(a3, wOwn[2 * m + 3], h1.y);
        }
        // wait: peer's h-half (stores from step t-1) now visible
        asm volatile("barrier.cluster.wait.aligned;" ::: "memory");
#pragma unroll
        for (int m = 0; m < 8; m += 2) {
            ulonglong2 h0 = *(const ulonglong2*)(hb + peerK + (4 * m + s) * 4);
            ulonglong2 h1 = *(const ulonglong2*)(hb + peerK + (4 * (m + 1) + s) * 4);
            fma2(a0, wPeer[2 * m],     h0.x);
            fma2(a1, wPeer[2 * m + 1], h0.y);
            fma2(a2, wPeer[2 * m + 2], h1.x);
            fma2(a3, wPeer[2 * m + 3], h1.y);
        }
        u64 aa = add2(add2(a0, a1), add2(a2, a3));
        float2 af = *(float2*)&aa;
        float sum = af.x + af.y;
        sum += __shfl_xor_sync(0xffffffffu, sum, 1);
        sum += __shfl_xor_sync(0xffffffffu, sum, 2);

        float v = tanhf(sum + xp_cur);      // all 4 group lanes compute (uniform)
        xp_cur = xp_next;
        if (writer) {
            hbuf[pn][ow] = v;               // local copy
            st_remote_f32(pn ? rH1 : rH0, v);  // peer copy (DSMEM)
        }
        __syncthreads();                    // local half visible CTA-wide
        asm volatile("barrier.cluster.arrive.aligned;" ::: "memory"); // release stores
    }
    asm volatile("barrier.cluster.wait.aligned;" ::: "memory");  // final exchange visible

    // classifier: rank 0 has the full final h
    if (rank == 0 && tid < 64) {
        int c = tid >> 5, lane = tid & 31;
        const float* hf = hbuf[len & 1];
        float sum = 0.0f;
#pragma unroll
        for (int m = 0; m < 8; m++)
            sum += Wcls[c * HDIM + lane + 32 * m] * hf[lane + 32 * m];
#pragma unroll
        for (int o = 16; o > 0; o >>= 1) sum += __shfl_down_sync(0xffffffffu, sum, o);
        if (lane == 0) out[b * 2 + c] = sum + bcls[c];
    }

    // keep both CTAs alive until all cross-CTA traffic has landed
    asm volatile("barrier.cluster.arrive.aligned;" ::: "memory");
    asm volatile("barrier.cluster.wait.aligned;" ::: "memory");
}

// ---------------------------------------------------------------------------
extern "C" void kernel_launch(void* const* d_in, const int* in_sizes, int n_in,
                              void* d_out, int out_size) {
    const int*   reviews = (const int*)d_in[0];
    const int*   lengths = (const int*)d_in[1];
    const float* emb     = (const float*)d_in[2];
    const float* Wih     = (const float*)d_in[3];
    const float* Whh     = (const float*)d_in[4];
    const float* Wcls    = (const float*)d_in[5];
    const float* bcls    = (const float*)d_in[6];
    float*       out     = (float*)d_out;

    dim3 gA(2, (VOCAB + 127) / 128);
    proj_kernel<<<gA, 256>>>(emb, Wih);

    scan_kernel<<<BATCH * 2, 512>>>(reviews, lengths, Whh, Wcls, bcls, out);
}